// round 1
// baseline (speedup 1.0000x reference)
#include <cuda_runtime.h>
#include <cuda_bf16.h>
#include <cstddef>

#define D 128
#define EPS 1e-5f
#define MAX_NODES 51200

// Scratch: reused in-place agg -> h1 -> h (each stage reads its row tile fully
// before overwriting it).
__device__ float g_scratch[(size_t)MAX_NODES * D];
__device__ float g_chsum[D];
__device__ float g_chsumsq[D];
__device__ float g_sc[D];
__device__ float g_sh[D];
__device__ int   g_idx64;

// ---------------------------------------------------------------------------
// Detect whether edge_index is int64 or int32 (jax x64 flag ambiguity).
// If the data is really int32, reinterpreting as int64 packs two indices per
// word -> values >= n_nodes almost surely within 64 samples.
__global__ void detect_idx_kernel(const long long* idx, int n_nodes) {
    int ok = 1;
    for (int i = 0; i < 64; ++i) {
        long long v = idx[i];
        if (v < 0 || v >= n_nodes) { ok = 0; break; }
    }
    g_idx64 = ok;
}

// ---------------------------------------------------------------------------
__global__ void zero_kernel(int total4) {
    float4* p = reinterpret_cast<float4*>(g_scratch);
    int stride = gridDim.x * blockDim.x;
    for (int i = blockIdx.x * blockDim.x + threadIdx.x; i < total4; i += stride) {
        p[i] = make_float4(0.f, 0.f, 0.f, 0.f);
    }
    if (blockIdx.x == 0 && threadIdx.x < D) {
        g_chsum[threadIdx.x] = 0.f;
        g_chsumsq[threadIdx.x] = 0.f;
    }
}

// ---------------------------------------------------------------------------
// One warp per edge: 32 lanes x float4 = 128 floats.
__global__ __launch_bounds__(256) void scatter_kernel(
    const float* __restrict__ node,
    const float* __restrict__ edge_h,
    const void* __restrict__ idx,
    int n_edges
) {
    int e    = (blockIdx.x * blockDim.x + threadIdx.x) >> 5;
    int lane = threadIdx.x & 31;
    if (e >= n_edges) return;

    long long src, dst;
    if (g_idx64) {
        const long long* p = reinterpret_cast<const long long*>(idx);
        src = p[e];
        dst = p[n_edges + e];
    } else {
        const int* p = reinterpret_cast<const int*>(idx);
        src = p[e];
        dst = p[n_edges + e];
    }

    float4 a = reinterpret_cast<const float4*>(node + (size_t)src * D)[lane];
    float4 b = reinterpret_cast<const float4*>(edge_h + (size_t)e * D)[lane];
    float4 m = make_float4(a.x + b.x, a.y + b.y, a.z + b.z, a.w + b.w);
    atomicAdd(reinterpret_cast<float4*>(g_scratch + (size_t)dst * D) + lane, m);
}

// ---------------------------------------------------------------------------
// Register-tiled fp32 GEMM (in-place on g_scratch).
// Block: 256 threads, tile 64 rows x 128 cols, thread tile 8x4.
// LAYER 1: +bias, ReLU.  LAYER 2: +bias, LayerNorm, GraphNorm channel stats.
#define TILE_ROWS 64
#define A_LD 68                     // padded k-major lda (float4-aligned)
#define GEMM_SMEM_FLOATS (128*128 + 128*A_LD + 2*8*128)
#define GEMM_SMEM_BYTES  (GEMM_SMEM_FLOATS * sizeof(float))

template<int LAYER>
__global__ __launch_bounds__(256, 2) void gemm_kernel(
    const float* __restrict__ w,
    const float* __restrict__ bias,
    const float* __restrict__ lng,
    const float* __restrict__ lnb,
    int n
) {
    extern __shared__ float sm[];
    float* w_s  = sm;                       // 128*128
    float* a_s  = sm + 128 * 128;           // 128*A_LD, k-major (transposed tile)
    float* s_ps = a_s + 128 * A_LD;         // 8*128 channel-sum partials
    float* s_pq = s_ps + 8 * 128;           // 8*128 channel-sumsq partials
    __shared__ float s_bias[D];
    __shared__ float s_g[D];
    __shared__ float s_b[D];

    int tid = threadIdx.x;

    // Load weights (64KB) once per block.
    for (int i = tid; i < 128 * 128; i += 256) w_s[i] = w[i];
    if (tid < D) {
        s_bias[tid] = bias[tid];
        if (LAYER == 2) { s_g[tid] = lng[tid]; s_b[tid] = lnb[tid]; }
    }

    int col = (tid & 31) * 4;   // output columns col..col+3
    int rg  = tid >> 5;         // row group 0..7 (rows rg*8..rg*8+7)
    int num_tiles = (n + TILE_ROWS - 1) / TILE_ROWS;

    for (int tile = blockIdx.x; tile < num_tiles; tile += gridDim.x) {
        int row0 = tile * TILE_ROWS;

        __syncthreads();  // protect a_s readers of previous tile
        // Load input tile transposed: a_s[k][r]
        for (int i = tid; i < TILE_ROWS * 128; i += 256) {
            int r = i >> 7, k = i & 127;
            int row = row0 + r;
            a_s[k * A_LD + r] = (row < n) ? g_scratch[(size_t)row * D + k] : 0.f;
        }
        __syncthreads();

        float acc[8][4];
        #pragma unroll
        for (int r = 0; r < 8; ++r)
            #pragma unroll
            for (int c = 0; c < 4; ++c) acc[r][c] = 0.f;

        #pragma unroll 8
        for (int k = 0; k < 128; ++k) {
            float4 wv = *reinterpret_cast<const float4*>(w_s + k * 128 + col);
            float4 aa = *reinterpret_cast<const float4*>(a_s + k * A_LD + rg * 8);
            float4 ab = *reinterpret_cast<const float4*>(a_s + k * A_LD + rg * 8 + 4);
            float ar[8] = {aa.x, aa.y, aa.z, aa.w, ab.x, ab.y, ab.z, ab.w};
            #pragma unroll
            for (int r = 0; r < 8; ++r) {
                acc[r][0] = fmaf(ar[r], wv.x, acc[r][0]);
                acc[r][1] = fmaf(ar[r], wv.y, acc[r][1]);
                acc[r][2] = fmaf(ar[r], wv.z, acc[r][2]);
                acc[r][3] = fmaf(ar[r], wv.w, acc[r][3]);
            }
        }

        if (LAYER == 1) {
            #pragma unroll
            for (int r = 0; r < 8; ++r) {
                int row = row0 + rg * 8 + r;
                if (row < n) {
                    float4 v;
                    v.x = fmaxf(acc[r][0] + s_bias[col + 0], 0.f);
                    v.y = fmaxf(acc[r][1] + s_bias[col + 1], 0.f);
                    v.z = fmaxf(acc[r][2] + s_bias[col + 2], 0.f);
                    v.w = fmaxf(acc[r][3] + s_bias[col + 3], 0.f);
                    *reinterpret_cast<float4*>(g_scratch + (size_t)row * D + col) = v;
                }
            }
        } else {
            float cs[4] = {0.f, 0.f, 0.f, 0.f};
            float cq[4] = {0.f, 0.f, 0.f, 0.f};
            #pragma unroll
            for (int r = 0; r < 8; ++r) {
                int row = row0 + rg * 8 + r;
                if (row < n) {
                    float v0 = acc[r][0] + s_bias[col + 0];
                    float v1 = acc[r][1] + s_bias[col + 1];
                    float v2 = acc[r][2] + s_bias[col + 2];
                    float v3 = acc[r][3] + s_bias[col + 3];
                    float s = v0 + v1 + v2 + v3;
                    float q = v0*v0 + v1*v1 + v2*v2 + v3*v3;
                    #pragma unroll
                    for (int m = 16; m >= 1; m >>= 1) {
                        s += __shfl_xor_sync(0xffffffffu, s, m);
                        q += __shfl_xor_sync(0xffffffffu, q, m);
                    }
                    float mean = s * (1.f / 128.f);
                    float var  = q * (1.f / 128.f) - mean * mean;
                    float rs   = rsqrtf(var + EPS);
                    v0 = (v0 - mean) * rs * s_g[col + 0] + s_b[col + 0];
                    v1 = (v1 - mean) * rs * s_g[col + 1] + s_b[col + 1];
                    v2 = (v2 - mean) * rs * s_g[col + 2] + s_b[col + 2];
                    v3 = (v3 - mean) * rs * s_g[col + 3] + s_b[col + 3];
                    float4 v = make_float4(v0, v1, v2, v3);
                    *reinterpret_cast<float4*>(g_scratch + (size_t)row * D + col) = v;
                    cs[0] += v0; cs[1] += v1; cs[2] += v2; cs[3] += v3;
                    cq[0] += v0*v0; cq[1] += v1*v1; cq[2] += v2*v2; cq[3] += v3*v3;
                }
            }
            #pragma unroll
            for (int c = 0; c < 4; ++c) {
                s_ps[rg * 128 + col + c] = cs[c];
                s_pq[rg * 128 + col + c] = cq[c];
            }
            __syncthreads();
            if (tid < 128) {
                float s = 0.f, q = 0.f;
                #pragma unroll
                for (int g = 0; g < 8; ++g) {
                    s += s_ps[g * 128 + tid];
                    q += s_pq[g * 128 + tid];
                }
                atomicAdd(&g_chsum[tid], s);
                atomicAdd(&g_chsumsq[tid], q);
            }
        }
    }
}

// ---------------------------------------------------------------------------
// GraphNorm stats -> per-channel affine (scale, shift).
// gvar = E[h^2] - (2a - a^2) * gmu^2   since E[h] = gmu, centered = h - a*gmu.
__global__ void gn_stats_kernel(
    const float* __restrict__ gn_w,
    const float* __restrict__ gn_b,
    const float* __restrict__ gn_ms,
    int n
) {
    int j = threadIdx.x;
    float inv_n = 1.f / (float)n;
    float mu  = g_chsum[j] * inv_n;
    float eh2 = g_chsumsq[j] * inv_n;
    float a   = gn_ms[j];
    float var = eh2 - (2.f * a - a * a) * mu * mu;
    float inv = rsqrtf(var + EPS);
    float s   = inv * gn_w[j];
    g_sc[j] = s;
    g_sh[j] = gn_b[j] - a * mu * s;
}

// ---------------------------------------------------------------------------
__global__ void final_kernel(const float* __restrict__ node, float* __restrict__ out, int total4) {
    __shared__ float s_sc[D];
    __shared__ float s_sh[D];
    if (threadIdx.x < D) {
        s_sc[threadIdx.x] = g_sc[threadIdx.x];
        s_sh[threadIdx.x] = g_sh[threadIdx.x];
    }
    __syncthreads();
    int stride = gridDim.x * blockDim.x;
    for (int i = blockIdx.x * blockDim.x + threadIdx.x; i < total4; i += stride) {
        float4 hv = reinterpret_cast<const float4*>(g_scratch)[i];
        float4 nv = reinterpret_cast<const float4*>(node)[i];
        int j = (i & 31) * 4;
        float4 o;
        o.x = fmaxf(hv.x * s_sc[j + 0] + s_sh[j + 0], 0.f) + nv.x;
        o.y = fmaxf(hv.y * s_sc[j + 1] + s_sh[j + 1], 0.f) + nv.y;
        o.z = fmaxf(hv.z * s_sc[j + 2] + s_sh[j + 2], 0.f) + nv.z;
        o.w = fmaxf(hv.w * s_sc[j + 3] + s_sh[j + 3], 0.f) + nv.w;
        reinterpret_cast<float4*>(out)[i] = o;
    }
}

// ---------------------------------------------------------------------------
extern "C" void kernel_launch(void* const* d_in, const int* in_sizes, int n_in,
                              void* d_out, int out_size) {
    const float* node  = (const float*)d_in[0];
    const float* edgeh = (const float*)d_in[1];
    const float* w1    = (const float*)d_in[2];
    const float* b1    = (const float*)d_in[3];
    const float* w2    = (const float*)d_in[4];
    const float* b2    = (const float*)d_in[5];
    const float* lng   = (const float*)d_in[6];
    const float* lnb   = (const float*)d_in[7];
    const float* gnw   = (const float*)d_in[8];
    const float* gnb   = (const float*)d_in[9];
    const float* gnms  = (const float*)d_in[10];
    const void*  idx   = d_in[11];

    int n = in_sizes[0] / D;   // 50000
    int e = in_sizes[1] / D;   // 600000

    cudaFuncSetAttribute(gemm_kernel<1>, cudaFuncAttributeMaxDynamicSharedMemorySize, GEMM_SMEM_BYTES);
    cudaFuncSetAttribute(gemm_kernel<2>, cudaFuncAttributeMaxDynamicSharedMemorySize, GEMM_SMEM_BYTES);

    detect_idx_kernel<<<1, 1>>>((const long long*)idx, n);
    zero_kernel<<<2048, 256>>>(n * (D / 4));
    scatter_kernel<<<(e + 7) / 8, 256>>>(node, edgeh, idx, e);
    gemm_kernel<1><<<304, 256, GEMM_SMEM_BYTES>>>(w1, b1, lng, lnb, n);
    gemm_kernel<2><<<304, 256, GEMM_SMEM_BYTES>>>(w2, b2, lng, lnb, n);
    gn_stats_kernel<<<1, D>>>(gnw, gnb, gnms, n);
    final_kernel<<<2048, 256>>>(node, (float*)d_out, n * (D / 4));
}

// round 4
// speedup vs baseline: 1.0066x; 1.0066x over previous
#include <cuda_runtime.h>
#include <cstdint>
#include <cstddef>

#define D 128
#define EPS 1e-5f
#define MAX_NODES 51200

#if defined(__CUDA_ARCH__) && defined(__CUDA_ARCH_FEAT_SM103_ALL)
#define HAS_TCGEN05 1
#else
#define HAS_TCGEN05 0
#endif

// Scratch reused in-place: agg -> h1 -> h
__device__ float g_scratch[(size_t)MAX_NODES * D];
__device__ float g_chsum[D];
__device__ float g_chsumsq[D];
__device__ float g_sc[D];
__device__ float g_sh[D];
__device__ int   g_idx64;
__device__ int   g_use_tc;

// ---------------------------------------------------------------------------
// helpers
__device__ __forceinline__ uint32_t smem_u32(const void* p) {
    uint32_t a;
    asm("{ .reg .u64 t; cvta.to.shared.u64 t, %1; cvt.u32.u64 %0, t; }" : "=r"(a) : "l"(p));
    return a;
}
__device__ __forceinline__ uint32_t sw128(uint32_t off) { return off ^ ((off >> 3) & 0x70u); }

#if HAS_TCGEN05
#define TC_ALLOC(smem_addr, ncols) \
    asm volatile("tcgen05.alloc.cta_group::1.sync.aligned.shared::cta.b32 [%0], %1;" \
        :: "r"(smem_addr), "r"((uint32_t)(ncols)) : "memory")
#define TC_DEALLOC(tmem, ncols) \
    asm volatile("tcgen05.dealloc.cta_group::1.sync.aligned.b32 %0, %1;" \
        :: "r"(tmem), "r"((uint32_t)(ncols)))
#define TC_COMMIT(mbar) \
    asm volatile("tcgen05.commit.cta_group::1.mbarrier::arrive::one.shared::cluster.b64 [%0];" \
        :: "r"(mbar) : "memory")
#define TC_FENCE_AFTER()  asm volatile("tcgen05.fence::after_thread_sync;" ::: "memory")
#define TC_FENCE_BEFORE() asm volatile("tcgen05.fence::before_thread_sync;" ::: "memory")
#define TC_WAIT_LD()      asm volatile("tcgen05.wait::ld.sync.aligned;" ::: "memory")

__device__ __forceinline__ void mma_tf32_ss(uint32_t d, uint64_t a, uint64_t b,
                                            uint32_t idesc, bool acc) {
    uint32_t en = acc ? 1u : 0u;
    asm volatile(
        "{\n\t.reg .pred p;\n\t"
        "setp.ne.u32 p, %4, 0;\n\t"
        "tcgen05.mma.cta_group::1.kind::tf32 [%0], %1, %2, %3, {%5, %5, %5, %5}, p;\n\t}"
        :: "r"(d), "l"(a), "l"(b), "r"(idesc), "r"(en), "r"(0u) : "memory");
}

#define LDTM_X32(r, addr) \
    asm volatile( \
        "tcgen05.ld.sync.aligned.32x32b.x32.b32 " \
        "{%0, %1, %2, %3, %4, %5, %6, %7, " \
        " %8, %9, %10, %11, %12, %13, %14, %15, " \
        " %16, %17, %18, %19, %20, %21, %22, %23, " \
        " %24, %25, %26, %27, %28, %29, %30, %31}, [%32];" \
        : "=r"((r)[0]),  "=r"((r)[1]),  "=r"((r)[2]),  "=r"((r)[3]), \
          "=r"((r)[4]),  "=r"((r)[5]),  "=r"((r)[6]),  "=r"((r)[7]), \
          "=r"((r)[8]),  "=r"((r)[9]),  "=r"((r)[10]), "=r"((r)[11]), \
          "=r"((r)[12]), "=r"((r)[13]), "=r"((r)[14]), "=r"((r)[15]), \
          "=r"((r)[16]), "=r"((r)[17]), "=r"((r)[18]), "=r"((r)[19]), \
          "=r"((r)[20]), "=r"((r)[21]), "=r"((r)[22]), "=r"((r)[23]), \
          "=r"((r)[24]), "=r"((r)[25]), "=r"((r)[26]), "=r"((r)[27]), \
          "=r"((r)[28]), "=r"((r)[29]), "=r"((r)[30]), "=r"((r)[31]) \
        : "r"(addr))
#endif  // HAS_TCGEN05

#define MBAR_INIT(mbar, cnt) \
    asm volatile("mbarrier.init.shared.b64 [%0], %1;" :: "r"(mbar), "r"((uint32_t)(cnt)) : "memory")

__device__ __forceinline__ void mbar_wait(uint32_t mbar, uint32_t parity) {
    asm volatile(
        "{\n\t.reg .pred P;\n\t"
        "WL_%=:\n\t"
        "mbarrier.try_wait.parity.acquire.cta.shared::cta.b64 P, [%0], %1, 0x989680;\n\t"
        "@P bra.uni WD_%=;\n\t"
        "bra.uni WL_%=;\n\t"
        "WD_%=:\n\t}"
        :: "r"(mbar), "r"(parity) : "memory");
}

// SMEM descriptor: SW128, version=1, SBO=64, LBO=1 (K-major)
static __device__ __forceinline__ uint64_t make_desc(uint32_t addr) {
    return (uint64_t(2) << 61) | (uint64_t(1) << 46) | (uint64_t(64) << 32)
         | (uint64_t(1) << 16) | ((uint64_t)(addr >> 4) & 0x3FFF);
}

// idesc: c=F32(1<<4), a=TF32(2<<7), b=TF32(2<<10), N=128 (16<<17), M=128 (8<<24)
#define IDESC_TF32 0x8200910u

// ---------------------------------------------------------------------------
__global__ void detect_idx_kernel(const long long* idx, int n_nodes) {
    int ok = 1;
    for (int i = 0; i < 64; ++i) {
        long long v = idx[i];
        if (v < 0 || v >= n_nodes) { ok = 0; break; }
    }
    g_idx64 = ok;
    g_use_tc = HAS_TCGEN05;
}

// ---------------------------------------------------------------------------
__global__ void zero_kernel(int total4) {
    float4* p = reinterpret_cast<float4*>(g_scratch);
    int stride = gridDim.x * blockDim.x;
    for (int i = blockIdx.x * blockDim.x + threadIdx.x; i < total4; i += stride)
        p[i] = make_float4(0.f, 0.f, 0.f, 0.f);
    if (blockIdx.x == 0 && threadIdx.x < D) {
        g_chsum[threadIdx.x] = 0.f;
        g_chsumsq[threadIdx.x] = 0.f;
    }
}

// ---------------------------------------------------------------------------
// One warp per edge: 32 lanes x float4 = 128 floats.
__global__ __launch_bounds__(256) void scatter_kernel(
    const float* __restrict__ node,
    const float* __restrict__ edge_h,
    const void* __restrict__ idx,
    int n_edges
) {
    int e    = (blockIdx.x * blockDim.x + threadIdx.x) >> 5;
    int lane = threadIdx.x & 31;
    if (e >= n_edges) return;

    long long src, dst;
    if (g_idx64) {
        const long long* p = reinterpret_cast<const long long*>(idx);
        src = p[e];
        dst = p[n_edges + e];
    } else {
        const int* p = reinterpret_cast<const int*>(idx);
        src = p[e];
        dst = p[n_edges + e];
    }

    float4 a = reinterpret_cast<const float4*>(node + (size_t)src * D)[lane];
    float4 b = reinterpret_cast<const float4*>(edge_h + (size_t)e * D)[lane];
    float4 m = make_float4(a.x + b.x, a.y + b.y, a.z + b.z, a.w + b.w);
    atomicAdd(reinterpret_cast<float4*>(g_scratch + (size_t)dst * D) + lane, m);
}

// ---------------------------------------------------------------------------
// tcgen05 tf32 GEMM, persistent CTAs, in-place on g_scratch. Only does work
// when compiled for sm_103a (HAS_TCGEN05); otherwise a stub.
#define GEMM_DYN_BYTES (2 * 128 * 128 * 4 + 1024)

template<int LAYER>
__global__ __launch_bounds__(128, 1) void gemm_tc(
    const float* __restrict__ w,
    const float* __restrict__ bias,
    const float* __restrict__ lng,
    const float* __restrict__ lnb,
    int n
) {
#if HAS_TCGEN05
    extern __shared__ float dyn[];
    uintptr_t ab = ((uintptr_t)dyn + 1023) & ~(uintptr_t)1023;
    float* b_s = (float*)ab;            // W^T swizzled, 64KB
    float* a_s = b_s + 128 * 128;       // A tile swizzled, 64KB
    __shared__ float s_bias[D], s_g[D], s_b[D];
    __shared__ uint32_t s_tmem;
    __shared__ __align__(8) unsigned long long s_mbar;

    int tid  = threadIdx.x;
    int wid  = tid >> 5;
    int lane = tid & 31;
    uint32_t mbar_u = smem_u32(&s_mbar);

    if (wid == 0) TC_ALLOC(smem_u32(&s_tmem), 128);
    if (tid == 0) MBAR_INIT(mbar_u, 1);
    if (tid < D) {
        s_bias[tid] = bias[tid];
        if (LAYER == 2) { s_g[tid] = lng[tid]; s_b[tid] = lnb[tid]; }
    }

    // Stage W coalesced into a_s (plain layout), then transpose+swizzle into b_s.
    for (int i = tid; i < 4096; i += 128)
        reinterpret_cast<float4*>(a_s)[i] = reinterpret_cast<const float4*>(w)[i];
    __syncthreads();
    uint32_t tmem = s_tmem;

    for (int i = tid; i < 4096; i += 128) {
        int kc = i >> 7, nn = i & 127;   // lanes vary nn -> conflict-free LDS
        int k0 = kc * 4;
        float4 v;
        v.x = a_s[(k0 + 0) * 128 + nn];
        v.y = a_s[(k0 + 1) * 128 + nn];
        v.z = a_s[(k0 + 2) * 128 + nn];
        v.w = a_s[(k0 + 3) * 128 + nn];
        uint32_t off = ((uint32_t)(nn >> 3) + (uint32_t)(k0 >> 5) * 16u) * 1024u
                     + (uint32_t)(nn & 7) * 128u + (uint32_t)(k0 & 31) * 4u;
        *reinterpret_cast<float4*>(reinterpret_cast<char*>(b_s) + sw128(off)) = v;
    }

    uint64_t a_desc0 = make_desc(smem_u32(a_s));
    uint64_t b_desc0 = make_desc(smem_u32(b_s));
    int ntiles = (n + 127) >> 7;
    uint32_t phase = 0;

    for (int tile = blockIdx.x; tile < ntiles; tile += gridDim.x) {
        int row0 = tile << 7;
        __syncthreads();   // prev MMA done (mbar) -> a_s reusable

        for (int i = tid; i < 4096; i += 128) {
            int r = i >> 5, c4 = i & 31;
            int k0 = c4 * 4;
            int row = row0 + r;
            float4 v = make_float4(0.f, 0.f, 0.f, 0.f);
            if (row < n) v = *reinterpret_cast<const float4*>(g_scratch + (size_t)row * D + k0);
            uint32_t off = ((uint32_t)(r >> 3) + (uint32_t)(k0 >> 5) * 16u) * 1024u
                         + (uint32_t)(r & 7) * 128u + (uint32_t)(k0 & 31) * 4u;
            *reinterpret_cast<float4*>(reinterpret_cast<char*>(a_s) + sw128(off)) = v;
        }
        asm volatile("fence.proxy.async.shared::cta;" ::: "memory");
        __syncthreads();

        if (tid == 0) {
            #pragma unroll
            for (int t = 0; t < 16; ++t) {
                uint64_t off = (uint64_t)((t >> 2) * 1024 + (t & 3) * 2);
                mma_tf32_ss(tmem, a_desc0 + off, b_desc0 + off, IDESC_TF32, t > 0);
            }
            TC_COMMIT(mbar_u);
        }
        mbar_wait(mbar_u, phase);
        phase ^= 1;
        TC_FENCE_AFTER();

        int row = row0 + wid * 32 + lane;
        if (LAYER == 1) {
            #pragma unroll
            for (int cb = 0; cb < 128; cb += 32) {
                uint32_t r32[32];
                LDTM_X32(r32, tmem + cb);
                TC_WAIT_LD();
                if (row < n) {
                    float* dst = g_scratch + (size_t)row * D + cb;
                    #pragma unroll
                    for (int j = 0; j < 8; ++j) {
                        float4 v;
                        v.x = fmaxf(__uint_as_float(r32[4 * j + 0]) + s_bias[cb + 4 * j + 0], 0.f);
                        v.y = fmaxf(__uint_as_float(r32[4 * j + 1]) + s_bias[cb + 4 * j + 1], 0.f);
                        v.z = fmaxf(__uint_as_float(r32[4 * j + 2]) + s_bias[cb + 4 * j + 2], 0.f);
                        v.w = fmaxf(__uint_as_float(r32[4 * j + 3]) + s_bias[cb + 4 * j + 3], 0.f);
                        reinterpret_cast<float4*>(dst)[j] = v;
                    }
                }
            }
        } else {
            uint32_t r32[128];
            LDTM_X32(r32 +  0, tmem +  0);
            LDTM_X32(r32 + 32, tmem + 32);
            LDTM_X32(r32 + 64, tmem + 64);
            LDTM_X32(r32 + 96, tmem + 96);
            TC_WAIT_LD();
            float sum = 0.f, sq = 0.f;
            #pragma unroll
            for (int c = 0; c < 128; ++c) {
                float v = __uint_as_float(r32[c]) + s_bias[c];
                r32[c] = __float_as_uint(v);
                sum += v;
                sq  += v * v;
            }
            float mean = sum * (1.f / 128.f);
            float var  = sq * (1.f / 128.f) - mean * mean;
            float rs   = rsqrtf(var + EPS);
            if (row < n) {
                float* dst = g_scratch + (size_t)row * D;
                #pragma unroll
                for (int j = 0; j < 32; ++j) {
                    float4 v;
                    v.x = (__uint_as_float(r32[4 * j + 0]) - mean) * rs * s_g[4 * j + 0] + s_b[4 * j + 0];
                    v.y = (__uint_as_float(r32[4 * j + 1]) - mean) * rs * s_g[4 * j + 1] + s_b[4 * j + 1];
                    v.z = (__uint_as_float(r32[4 * j + 2]) - mean) * rs * s_g[4 * j + 2] + s_b[4 * j + 2];
                    v.w = (__uint_as_float(r32[4 * j + 3]) - mean) * rs * s_g[4 * j + 3] + s_b[4 * j + 3];
                    reinterpret_cast<float4*>(dst)[j] = v;
                }
            }
        }
        TC_FENCE_BEFORE();
    }

    __syncthreads();
    if (wid == 0) TC_DEALLOC(tmem, 128);
#endif  // HAS_TCGEN05
}

// ---------------------------------------------------------------------------
// SIMT fallback GEMM (round-1 design; runs only when g_use_tc == 0).
#define TILE_ROWS 64
#define A_LD 68
#define SIMT_SMEM_FLOATS (128*128 + 128*A_LD + 2*8*128)
#define SIMT_SMEM_BYTES  (SIMT_SMEM_FLOATS * sizeof(float))

template<int LAYER>
__global__ __launch_bounds__(256, 2) void gemm_simt(
    const float* __restrict__ w,
    const float* __restrict__ bias,
    const float* __restrict__ lng,
    const float* __restrict__ lnb,
    int n
) {
    if (g_use_tc) return;
    extern __shared__ float sm[];
    float* w_s  = sm;
    float* a_s  = sm + 128 * 128;
    float* s_ps = a_s + 128 * A_LD;
    float* s_pq = s_ps + 8 * 128;
    __shared__ float s_bias[D], s_g[D], s_b[D];

    int tid = threadIdx.x;
    for (int i = tid; i < 128 * 128; i += 256) w_s[i] = w[i];
    if (tid < D) {
        s_bias[tid] = bias[tid];
        if (LAYER == 2) { s_g[tid] = lng[tid]; s_b[tid] = lnb[tid]; }
    }

    int col = (tid & 31) * 4;
    int rg  = tid >> 5;
    int num_tiles = (n + TILE_ROWS - 1) / TILE_ROWS;

    for (int tile = blockIdx.x; tile < num_tiles; tile += gridDim.x) {
        int row0 = tile * TILE_ROWS;
        __syncthreads();
        for (int i = tid; i < TILE_ROWS * 128; i += 256) {
            int r = i >> 7, k = i & 127;
            int row = row0 + r;
            a_s[k * A_LD + r] = (row < n) ? g_scratch[(size_t)row * D + k] : 0.f;
        }
        __syncthreads();

        float acc[8][4];
        #pragma unroll
        for (int r = 0; r < 8; ++r)
            #pragma unroll
            for (int c = 0; c < 4; ++c) acc[r][c] = 0.f;

        #pragma unroll 8
        for (int k = 0; k < 128; ++k) {
            float4 wv = *reinterpret_cast<const float4*>(w_s + k * 128 + col);
            float4 aa = *reinterpret_cast<const float4*>(a_s + k * A_LD + rg * 8);
            float4 ab = *reinterpret_cast<const float4*>(a_s + k * A_LD + rg * 8 + 4);
            float ar[8] = {aa.x, aa.y, aa.z, aa.w, ab.x, ab.y, ab.z, ab.w};
            #pragma unroll
            for (int r = 0; r < 8; ++r) {
                acc[r][0] = fmaf(ar[r], wv.x, acc[r][0]);
                acc[r][1] = fmaf(ar[r], wv.y, acc[r][1]);
                acc[r][2] = fmaf(ar[r], wv.z, acc[r][2]);
                acc[r][3] = fmaf(ar[r], wv.w, acc[r][3]);
            }
        }

        if (LAYER == 1) {
            #pragma unroll
            for (int r = 0; r < 8; ++r) {
                int row = row0 + rg * 8 + r;
                if (row < n) {
                    float4 v;
                    v.x = fmaxf(acc[r][0] + s_bias[col + 0], 0.f);
                    v.y = fmaxf(acc[r][1] + s_bias[col + 1], 0.f);
                    v.z = fmaxf(acc[r][2] + s_bias[col + 2], 0.f);
                    v.w = fmaxf(acc[r][3] + s_bias[col + 3], 0.f);
                    *reinterpret_cast<float4*>(g_scratch + (size_t)row * D + col) = v;
                }
            }
        } else {
            #pragma unroll
            for (int r = 0; r < 8; ++r) {
                int row = row0 + rg * 8 + r;
                if (row < n) {
                    float v0 = acc[r][0] + s_bias[col + 0];
                    float v1 = acc[r][1] + s_bias[col + 1];
                    float v2 = acc[r][2] + s_bias[col + 2];
                    float v3 = acc[r][3] + s_bias[col + 3];
                    float s = v0 + v1 + v2 + v3;
                    float q = v0*v0 + v1*v1 + v2*v2 + v3*v3;
                    #pragma unroll
                    for (int m = 16; m >= 1; m >>= 1) {
                        s += __shfl_xor_sync(0xffffffffu, s, m);
                        q += __shfl_xor_sync(0xffffffffu, q, m);
                    }
                    float mean = s * (1.f / 128.f);
                    float var  = q * (1.f / 128.f) - mean * mean;
                    float rs   = rsqrtf(var + EPS);
                    v0 = (v0 - mean) * rs * s_g[col + 0] + s_b[col + 0];
                    v1 = (v1 - mean) * rs * s_g[col + 1] + s_b[col + 1];
                    v2 = (v2 - mean) * rs * s_g[col + 2] + s_b[col + 2];
                    v3 = (v3 - mean) * rs * s_g[col + 3] + s_b[col + 3];
                    *reinterpret_cast<float4*>(g_scratch + (size_t)row * D + col) =
                        make_float4(v0, v1, v2, v3);
                }
            }
        }
    }
    (void)s_ps; (void)s_pq;
}

// ---------------------------------------------------------------------------
// GraphNorm channel sums over h (g_scratch).
__global__ __launch_bounds__(256) void chan_stats_kernel(int n) {
    __shared__ float ss[D], sq[D];
    int tid = threadIdx.x;
    if (tid < D) { ss[tid] = 0.f; sq[tid] = 0.f; }
    __syncthreads();

    int c4 = tid & 31;
    int gwarp  = (blockIdx.x * blockDim.x + tid) >> 5;
    int nwarps = (gridDim.x * blockDim.x) >> 5;
    float4 s = make_float4(0.f, 0.f, 0.f, 0.f);
    float4 q = make_float4(0.f, 0.f, 0.f, 0.f);
    for (int r = gwarp; r < n; r += nwarps) {
        float4 v = reinterpret_cast<const float4*>(g_scratch)[(size_t)r * 32 + c4];
        s.x += v.x; s.y += v.y; s.z += v.z; s.w += v.w;
        q.x += v.x * v.x; q.y += v.y * v.y; q.z += v.z * v.z; q.w += v.w * v.w;
    }
    atomicAdd(&ss[c4 * 4 + 0], s.x); atomicAdd(&sq[c4 * 4 + 0], q.x);
    atomicAdd(&ss[c4 * 4 + 1], s.y); atomicAdd(&sq[c4 * 4 + 1], q.y);
    atomicAdd(&ss[c4 * 4 + 2], s.z); atomicAdd(&sq[c4 * 4 + 2], q.z);
    atomicAdd(&ss[c4 * 4 + 3], s.w); atomicAdd(&sq[c4 * 4 + 3], q.w);
    __syncthreads();
    if (tid < D) {
        atomicAdd(&g_chsum[tid], ss[tid]);
        atomicAdd(&g_chsumsq[tid], sq[tid]);
    }
}

// ---------------------------------------------------------------------------
// gvar = E[h^2] - (2a - a^2) * gmu^2  (centered = h - a*gmu, E[h] = gmu)
__global__ void gn_stats_kernel(
    const float* __restrict__ gn_w,
    const float* __restrict__ gn_b,
    const float* __restrict__ gn_ms,
    int n
) {
    int j = threadIdx.x;
    float inv_n = 1.f / (float)n;
    float mu  = g_chsum[j] * inv_n;
    float eh2 = g_chsumsq[j] * inv_n;
    float a   = gn_ms[j];
    float var = eh2 - (2.f * a - a * a) * mu * mu;
    float inv = rsqrtf(var + EPS);
    float s   = inv * gn_w[j];
    g_sc[j] = s;
    g_sh[j] = gn_b[j] - a * mu * s;
}

// ---------------------------------------------------------------------------
__global__ void final_kernel(const float* __restrict__ node, float* __restrict__ out, int total4) {
    __shared__ float s_sc[D], s_sh[D];
    if (threadIdx.x < D) {
        s_sc[threadIdx.x] = g_sc[threadIdx.x];
        s_sh[threadIdx.x] = g_sh[threadIdx.x];
    }
    __syncthreads();
    int stride = gridDim.x * blockDim.x;
    for (int i = blockIdx.x * blockDim.x + threadIdx.x; i < total4; i += stride) {
        float4 hv = reinterpret_cast<const float4*>(g_scratch)[i];
        float4 nv = reinterpret_cast<const float4*>(node)[i];
        int j = (i & 31) * 4;
        float4 o;
        o.x = fmaxf(hv.x * s_sc[j + 0] + s_sh[j + 0], 0.f) + nv.x;
        o.y = fmaxf(hv.y * s_sc[j + 1] + s_sh[j + 1], 0.f) + nv.y;
        o.z = fmaxf(hv.z * s_sc[j + 2] + s_sh[j + 2], 0.f) + nv.z;
        o.w = fmaxf(hv.w * s_sc[j + 3] + s_sh[j + 3], 0.f) + nv.w;
        reinterpret_cast<float4*>(out)[i] = o;
    }
}

// ---------------------------------------------------------------------------
extern "C" void kernel_launch(void* const* d_in, const int* in_sizes, int n_in,
                              void* d_out, int out_size) {
    const float* node  = (const float*)d_in[0];
    const float* edgeh = (const float*)d_in[1];
    const float* w1    = (const float*)d_in[2];
    const float* b1    = (const float*)d_in[3];
    const float* w2    = (const float*)d_in[4];
    const float* b2    = (const float*)d_in[5];
    const float* lng   = (const float*)d_in[6];
    const float* lnb   = (const float*)d_in[7];
    const float* gnw   = (const float*)d_in[8];
    const float* gnb   = (const float*)d_in[9];
    const float* gnms  = (const float*)d_in[10];
    const void*  idx   = d_in[11];

    int n = in_sizes[0] / D;   // 50000
    int e = in_sizes[1] / D;   // 600000

    cudaFuncSetAttribute(gemm_tc<1>, cudaFuncAttributeMaxDynamicSharedMemorySize, GEMM_DYN_BYTES);
    cudaFuncSetAttribute(gemm_tc<2>, cudaFuncAttributeMaxDynamicSharedMemorySize, GEMM_DYN_BYTES);
    cudaFuncSetAttribute(gemm_simt<1>, cudaFuncAttributeMaxDynamicSharedMemorySize, SIMT_SMEM_BYTES);
    cudaFuncSetAttribute(gemm_simt<2>, cudaFuncAttributeMaxDynamicSharedMemorySize, SIMT_SMEM_BYTES);

    detect_idx_kernel<<<1, 1>>>((const long long*)idx, n);
    zero_kernel<<<2048, 256>>>(n * (D / 4));
    scatter_kernel<<<(e + 7) / 8, 256>>>(node, edgeh, idx, e);
    gemm_tc<1><<<148, 128, GEMM_DYN_BYTES>>>(w1, b1, lng, lnb, n);
    gemm_simt<1><<<304, 256, SIMT_SMEM_BYTES>>>(w1, b1, lng, lnb, n);
    gemm_tc<2><<<148, 128, GEMM_DYN_BYTES>>>(w2, b2, lng, lnb, n);
    gemm_simt<2><<<304, 256, SIMT_SMEM_BYTES>>>(w2, b2, lng, lnb, n);
    chan_stats_kernel<<<148, 256>>>(n);
    gn_stats_kernel<<<1, D>>>(gnw, gnb, gnms, n);
    final_kernel<<<2048, 256>>>(node, (float*)d_out, n * (D / 4));
}

// round 5
// speedup vs baseline: 1.0965x; 1.0894x over previous
#include <cuda_runtime.h>
#include <cstdint>
#include <cstddef>

#define D 128
#define EPS 1e-5f
#define MAX_NODES 51200

#if defined(__CUDA_ARCH__) && defined(__CUDA_ARCH_FEAT_SM103_ALL)
#define HAS_TCGEN05 1
#else
#define HAS_TCGEN05 0
#endif

// Scratch reused in-place: agg -> h1 -> h
__device__ float g_scratch[(size_t)MAX_NODES * D];
__device__ float g_chsum[D];
__device__ float g_chsumsq[D];
__device__ float g_sc[D];
__device__ float g_sh[D];
__device__ int   g_idx64;
__device__ int   g_use_tc;

// ---------------------------------------------------------------------------
__device__ __forceinline__ uint32_t smem_u32(const void* p) {
    uint32_t a;
    asm("{ .reg .u64 t; cvta.to.shared.u64 t, %1; cvt.u32.u64 %0, t; }" : "=r"(a) : "l"(p));
    return a;
}
__device__ __forceinline__ uint32_t sw128(uint32_t off) { return off ^ ((off >> 3) & 0x70u); }

#if HAS_TCGEN05
#define TC_ALLOC(smem_addr, ncols) \
    asm volatile("tcgen05.alloc.cta_group::1.sync.aligned.shared::cta.b32 [%0], %1;" \
        :: "r"(smem_addr), "r"((uint32_t)(ncols)) : "memory")
#define TC_DEALLOC(tmem, ncols) \
    asm volatile("tcgen05.dealloc.cta_group::1.sync.aligned.b32 %0, %1;" \
        :: "r"(tmem), "r"((uint32_t)(ncols)))
#define TC_COMMIT(mbar) \
    asm volatile("tcgen05.commit.cta_group::1.mbarrier::arrive::one.shared::cluster.b64 [%0];" \
        :: "r"(mbar) : "memory")
#define TC_FENCE_AFTER()  asm volatile("tcgen05.fence::after_thread_sync;" ::: "memory")
#define TC_FENCE_BEFORE() asm volatile("tcgen05.fence::before_thread_sync;" ::: "memory")
#define TC_WAIT_LD()      asm volatile("tcgen05.wait::ld.sync.aligned;" ::: "memory")

__device__ __forceinline__ void mma_tf32_ss(uint32_t d, uint64_t a, uint64_t b,
                                            uint32_t idesc, bool acc) {
    uint32_t en = acc ? 1u : 0u;
    asm volatile(
        "{\n\t.reg .pred p;\n\t"
        "setp.ne.u32 p, %4, 0;\n\t"
        "tcgen05.mma.cta_group::1.kind::tf32 [%0], %1, %2, %3, {%5, %5, %5, %5}, p;\n\t}"
        :: "r"(d), "l"(a), "l"(b), "r"(idesc), "r"(en), "r"(0u) : "memory");
}

#define LDTM_X32(r, addr) \
    asm volatile( \
        "tcgen05.ld.sync.aligned.32x32b.x32.b32 " \
        "{%0, %1, %2, %3, %4, %5, %6, %7, " \
        " %8, %9, %10, %11, %12, %13, %14, %15, " \
        " %16, %17, %18, %19, %20, %21, %22, %23, " \
        " %24, %25, %26, %27, %28, %29, %30, %31}, [%32];" \
        : "=r"((r)[0]),  "=r"((r)[1]),  "=r"((r)[2]),  "=r"((r)[3]), \
          "=r"((r)[4]),  "=r"((r)[5]),  "=r"((r)[6]),  "=r"((r)[7]), \
          "=r"((r)[8]),  "=r"((r)[9]),  "=r"((r)[10]), "=r"((r)[11]), \
          "=r"((r)[12]), "=r"((r)[13]), "=r"((r)[14]), "=r"((r)[15]), \
          "=r"((r)[16]), "=r"((r)[17]), "=r"((r)[18]), "=r"((r)[19]), \
          "=r"((r)[20]), "=r"((r)[21]), "=r"((r)[22]), "=r"((r)[23]), \
          "=r"((r)[24]), "=r"((r)[25]), "=r"((r)[26]), "=r"((r)[27]), \
          "=r"((r)[28]), "=r"((r)[29]), "=r"((r)[30]), "=r"((r)[31]) \
        : "r"(addr))
#endif  // HAS_TCGEN05

#define MBAR_INIT(mbar, cnt) \
    asm volatile("mbarrier.init.shared.b64 [%0], %1;" :: "r"(mbar), "r"((uint32_t)(cnt)) : "memory")

__device__ __forceinline__ void mbar_wait(uint32_t mbar, uint32_t parity) {
    asm volatile(
        "{\n\t.reg .pred P;\n\t"
        "WL_%=:\n\t"
        "mbarrier.try_wait.parity.acquire.cta.shared::cta.b64 P, [%0], %1, 0x989680;\n\t"
        "@P bra.uni WD_%=;\n\t"
        "bra.uni WL_%=;\n\t"
        "WD_%=:\n\t}"
        :: "r"(mbar), "r"(parity) : "memory");
}

// SMEM descriptor: SW128, version=1, SBO=64, LBO=1 (K-major)
static __device__ __forceinline__ uint64_t make_desc(uint32_t addr) {
    return (uint64_t(2) << 61) | (uint64_t(1) << 46) | (uint64_t(64) << 32)
         | (uint64_t(1) << 16) | ((uint64_t)(addr >> 4) & 0x3FFF);
}

// idesc: c=F32(1<<4), a=TF32(2<<7), b=TF32(2<<10), N=128 (16<<17), M=128 (8<<24)
#define IDESC_TF32 0x8200910u

// ---------------------------------------------------------------------------
__global__ void detect_idx_kernel(const long long* idx, int n_nodes) {
    int ok = 1;
    for (int i = 0; i < 64; ++i) {
        long long v = idx[i];
        if (v < 0 || v >= n_nodes) { ok = 0; break; }
    }
    g_idx64 = ok;
    g_use_tc = HAS_TCGEN05;
}

// ---------------------------------------------------------------------------
__global__ void zero_kernel(int total4) {
    float4* p = reinterpret_cast<float4*>(g_scratch);
    int stride = gridDim.x * blockDim.x;
    for (int i = blockIdx.x * blockDim.x + threadIdx.x; i < total4; i += stride)
        p[i] = make_float4(0.f, 0.f, 0.f, 0.f);
    if (blockIdx.x == 0 && threadIdx.x < D) {
        g_chsum[threadIdx.x] = 0.f;
        g_chsumsq[threadIdx.x] = 0.f;
    }
}

// ---------------------------------------------------------------------------
// One warp per edge: 32 lanes x float4 = 128 floats.
__global__ __launch_bounds__(256) void scatter_kernel(
    const float* __restrict__ node,
    const float* __restrict__ edge_h,
    const void* __restrict__ idx,
    int n_edges
) {
    int e    = (blockIdx.x * blockDim.x + threadIdx.x) >> 5;
    int lane = threadIdx.x & 31;
    if (e >= n_edges) return;

    long long src, dst;
    if (g_idx64) {
        const long long* p = reinterpret_cast<const long long*>(idx);
        src = p[e];
        dst = p[n_edges + e];
    } else {
        const int* p = reinterpret_cast<const int*>(idx);
        src = p[e];
        dst = p[n_edges + e];
    }

    float4 a = reinterpret_cast<const float4*>(node + (size_t)src * D)[lane];
    float4 b = reinterpret_cast<const float4*>(edge_h + (size_t)e * D)[lane];
    float4 m = make_float4(a.x + b.x, a.y + b.y, a.z + b.z, a.w + b.w);
    atomicAdd(reinterpret_cast<float4*>(g_scratch + (size_t)dst * D) + lane, m);
}

// ---------------------------------------------------------------------------
// tcgen05 tf32 GEMM, persistent CTAs, double-buffered software pipeline.
// SMEM: W^T (64KB) + A0 (64KB) + A1 (64KB). TMEM: D0 cols 0-127, D1 cols 128-255.
// Iter: load A[next] | issue MMA[next] | wait mb[cur] | epilogue D[cur].
#define GEMM_DYN_BYTES (3 * 128 * 128 * 4 + 1024)

template<int LAYER>
__global__ __launch_bounds__(256, 1) void gemm_tc(
    const float* __restrict__ w,
    const float* __restrict__ bias,
    const float* __restrict__ lng,
    const float* __restrict__ lnb,
    int n
) {
#if HAS_TCGEN05
    extern __shared__ float dyn[];
    uintptr_t ab = ((uintptr_t)dyn + 1023) & ~(uintptr_t)1023;
    float* b_s = (float*)ab;            // W^T swizzled, 64KB
    float* a_s0 = b_s + 128 * 128;      // A tile buf 0
    float* a_s1 = a_s0 + 128 * 128;     // A tile buf 1
    __shared__ float s_bias[D], s_g[D], s_b[D];
    __shared__ float s_sum[256], s_sq[256];
    __shared__ uint32_t s_tmem;
    __shared__ __align__(8) unsigned long long s_mbar[2];

    int tid  = threadIdx.x;
    int wid  = tid >> 5;
    int lane = tid & 31;
    uint32_t mb0 = smem_u32(&s_mbar[0]);
    uint32_t mb1 = smem_u32(&s_mbar[1]);

    if (wid == 0) TC_ALLOC(smem_u32(&s_tmem), 256);
    if (tid == 0) { MBAR_INIT(mb0, 1); MBAR_INIT(mb1, 1); }
    if (tid < D) {
        s_bias[tid] = bias[tid];
        if (LAYER == 2) { s_g[tid] = lng[tid]; s_b[tid] = lnb[tid]; }
    }

    // Stage W coalesced into a_s0 (plain), then transpose+swizzle into b_s.
    for (int i = tid; i < 4096; i += 256)
        reinterpret_cast<float4*>(a_s0)[i] = reinterpret_cast<const float4*>(w)[i];
    __syncthreads();
    uint32_t tmem = s_tmem;

    for (int i = tid; i < 4096; i += 256) {
        int kc = i >> 7, nn = i & 127;
        int k0 = kc * 4;
        float4 v;
        v.x = a_s0[(k0 + 0) * 128 + nn];
        v.y = a_s0[(k0 + 1) * 128 + nn];
        v.z = a_s0[(k0 + 2) * 128 + nn];
        v.w = a_s0[(k0 + 3) * 128 + nn];
        uint32_t off = ((uint32_t)(nn >> 3) + (uint32_t)(k0 >> 5) * 16u) * 1024u
                     + (uint32_t)(nn & 7) * 128u + (uint32_t)(k0 & 31) * 4u;
        *reinterpret_cast<float4*>(reinterpret_cast<char*>(b_s) + sw128(off)) = v;
    }
    __syncthreads();   // transpose reads of a_s0 done before tile-0 load overwrites

    uint64_t b_desc0 = make_desc(smem_u32(b_s));
    uint64_t a_desc[2] = { make_desc(smem_u32(a_s0)), make_desc(smem_u32(a_s1)) };
    float* a_buf[2] = { a_s0, a_s1 };
    int ntiles = (n + 127) >> 7;
    int gstride = gridDim.x;

    // per-warp epilogue split: warps 0-3 cols 0-63, warps 4-7 cols 64-127
    int w4  = wid & 3;
    int cb0 = (wid >> 2) * 64;

    int tile = blockIdx.x;
    if (tile < ntiles) {
        // ---- prologue: load tile0 into buf0, MMA -> D0
        {
            float* a_s = a_buf[0];
            int row0 = tile << 7;
            for (int i = tid; i < 4096; i += 256) {
                int r = i >> 5, c4 = i & 31;
                int k0 = c4 * 4;
                int row = row0 + r;
                float4 v = make_float4(0.f, 0.f, 0.f, 0.f);
                if (row < n) v = *reinterpret_cast<const float4*>(g_scratch + (size_t)row * D + k0);
                uint32_t off = ((uint32_t)(r >> 3) + (uint32_t)(k0 >> 5) * 16u) * 1024u
                             + (uint32_t)(r & 7) * 128u + (uint32_t)(k0 & 31) * 4u;
                *reinterpret_cast<float4*>(reinterpret_cast<char*>(a_s) + sw128(off)) = v;
            }
            asm volatile("fence.proxy.async.shared::cta;" ::: "memory");
            __syncthreads();
            if (tid == 0) {
                #pragma unroll
                for (int t = 0; t < 16; ++t) {
                    uint64_t off = (uint64_t)((t >> 2) * 1024 + (t & 3) * 2);
                    mma_tf32_ss(tmem, a_desc[0] + off, b_desc0 + off, IDESC_TF32, t > 0);
                }
                TC_COMMIT(mb0);
            }
        }

        uint32_t ph[2] = { 0u, 0u };
        int buf = 0;
        while (tile < ntiles) {
            int next = tile + gstride;
            int nbuf = buf ^ 1;
            if (next < ntiles) {
                // load A[next] (overlaps MMA[tile]); buffer free: its MMA waited 2 iters ago
                float* a_s = a_buf[nbuf];
                int row0n = next << 7;
                for (int i = tid; i < 4096; i += 256) {
                    int r = i >> 5, c4 = i & 31;
                    int k0 = c4 * 4;
                    int row = row0n + r;
                    float4 v = make_float4(0.f, 0.f, 0.f, 0.f);
                    if (row < n) v = *reinterpret_cast<const float4*>(g_scratch + (size_t)row * D + k0);
                    uint32_t off = ((uint32_t)(r >> 3) + (uint32_t)(k0 >> 5) * 16u) * 1024u
                                 + (uint32_t)(r & 7) * 128u + (uint32_t)(k0 & 31) * 4u;
                    *reinterpret_cast<float4*>(reinterpret_cast<char*>(a_s) + sw128(off)) = v;
                }
                asm volatile("fence.proxy.async.shared::cta;" ::: "memory");
                __syncthreads();
                if (tid == 0) {
                    uint32_t daddr = tmem + (uint32_t)nbuf * 128u;
                    #pragma unroll
                    for (int t = 0; t < 16; ++t) {
                        uint64_t off = (uint64_t)((t >> 2) * 1024 + (t & 3) * 2);
                        mma_tf32_ss(daddr, a_desc[nbuf] + off, b_desc0 + off, IDESC_TF32, t > 0);
                    }
                    TC_COMMIT(nbuf ? mb1 : mb0);
                }
            }

            // wait current tile's MMA, run epilogue on D[buf]
            mbar_wait(buf ? mb1 : mb0, ph[buf]);
            ph[buf] ^= 1;
            TC_FENCE_AFTER();

            uint32_t dbase = tmem + (uint32_t)buf * 128u + (uint32_t)cb0;
            int row0 = tile << 7;
            int row  = row0 + w4 * 32 + lane;

            uint32_t r32[64];
            LDTM_X32(r32,      dbase);
            LDTM_X32(r32 + 32, dbase + 32);
            TC_WAIT_LD();

            if (LAYER == 1) {
                if (row < n) {
                    float* dst = g_scratch + (size_t)row * D + cb0;
                    #pragma unroll
                    for (int j = 0; j < 16; ++j) {
                        float4 v;
                        v.x = fmaxf(__uint_as_float(r32[4*j+0]) + s_bias[cb0 + 4*j+0], 0.f);
                        v.y = fmaxf(__uint_as_float(r32[4*j+1]) + s_bias[cb0 + 4*j+1], 0.f);
                        v.z = fmaxf(__uint_as_float(r32[4*j+2]) + s_bias[cb0 + 4*j+2], 0.f);
                        v.w = fmaxf(__uint_as_float(r32[4*j+3]) + s_bias[cb0 + 4*j+3], 0.f);
                        reinterpret_cast<float4*>(dst)[j] = v;
                    }
                }
            } else {
                float sum = 0.f, sq = 0.f;
                #pragma unroll
                for (int c = 0; c < 64; ++c) {
                    float v = __uint_as_float(r32[c]) + s_bias[cb0 + c];
                    r32[c] = __float_as_uint(v);
                    sum += v;
                    sq  += v * v;
                }
                s_sum[tid] = sum;
                s_sq[tid]  = sq;
                __syncthreads();
                float S = s_sum[tid] + s_sum[tid ^ 128];
                float Q = s_sq[tid]  + s_sq[tid ^ 128];
                float mean = S * (1.f / 128.f);
                float var  = Q * (1.f / 128.f) - mean * mean;
                float rs   = rsqrtf(var + EPS);
                if (row < n) {
                    float* dst = g_scratch + (size_t)row * D + cb0;
                    #pragma unroll
                    for (int j = 0; j < 16; ++j) {
                        float4 v;
                        v.x = (__uint_as_float(r32[4*j+0]) - mean) * rs * s_g[cb0+4*j+0] + s_b[cb0+4*j+0];
                        v.y = (__uint_as_float(r32[4*j+1]) - mean) * rs * s_g[cb0+4*j+1] + s_b[cb0+4*j+1];
                        v.z = (__uint_as_float(r32[4*j+2]) - mean) * rs * s_g[cb0+4*j+2] + s_b[cb0+4*j+2];
                        v.w = (__uint_as_float(r32[4*j+3]) - mean) * rs * s_g[cb0+4*j+3] + s_b[cb0+4*j+3];
                        reinterpret_cast<float4*>(dst)[j] = v;
                    }
                }
            }
            TC_FENCE_BEFORE();
            __syncthreads();   // all LDTMs done before next iteration reuses D[buf]

            tile = next;
            buf  = nbuf;
        }
    }

    __syncthreads();
    if (wid == 0) TC_DEALLOC(tmem, 256);
#endif  // HAS_TCGEN05
}

// ---------------------------------------------------------------------------
// SIMT fallback GEMM (runs only when g_use_tc == 0).
#define TILE_ROWS 64
#define A_LD 68
#define SIMT_SMEM_FLOATS (128*128 + 128*A_LD)
#define SIMT_SMEM_BYTES  (SIMT_SMEM_FLOATS * sizeof(float))

template<int LAYER>
__global__ __launch_bounds__(256, 2) void gemm_simt(
    const float* __restrict__ w,
    const float* __restrict__ bias,
    const float* __restrict__ lng,
    const float* __restrict__ lnb,
    int n
) {
    if (g_use_tc) return;
    extern __shared__ float sm[];
    float* w_s  = sm;
    float* a_s  = sm + 128 * 128;
    __shared__ float s_bias[D], s_g[D], s_b[D];

    int tid = threadIdx.x;
    for (int i = tid; i < 128 * 128; i += 256) w_s[i] = w[i];
    if (tid < D) {
        s_bias[tid] = bias[tid];
        if (LAYER == 2) { s_g[tid] = lng[tid]; s_b[tid] = lnb[tid]; }
    }

    int col = (tid & 31) * 4;
    int rg  = tid >> 5;
    int num_tiles = (n + TILE_ROWS - 1) / TILE_ROWS;

    for (int tile = blockIdx.x; tile < num_tiles; tile += gridDim.x) {
        int row0 = tile * TILE_ROWS;
        __syncthreads();
        for (int i = tid; i < TILE_ROWS * 128; i += 256) {
            int r = i >> 7, k = i & 127;
            int row = row0 + r;
            a_s[k * A_LD + r] = (row < n) ? g_scratch[(size_t)row * D + k] : 0.f;
        }
        __syncthreads();

        float acc[8][4];
        #pragma unroll
        for (int r = 0; r < 8; ++r)
            #pragma unroll
            for (int c = 0; c < 4; ++c) acc[r][c] = 0.f;

        #pragma unroll 8
        for (int k = 0; k < 128; ++k) {
            float4 wv = *reinterpret_cast<const float4*>(w_s + k * 128 + col);
            float4 aa = *reinterpret_cast<const float4*>(a_s + k * A_LD + rg * 8);
            float4 ab = *reinterpret_cast<const float4*>(a_s + k * A_LD + rg * 8 + 4);
            float ar[8] = {aa.x, aa.y, aa.z, aa.w, ab.x, ab.y, ab.z, ab.w};
            #pragma unroll
            for (int r = 0; r < 8; ++r) {
                acc[r][0] = fmaf(ar[r], wv.x, acc[r][0]);
                acc[r][1] = fmaf(ar[r], wv.y, acc[r][1]);
                acc[r][2] = fmaf(ar[r], wv.z, acc[r][2]);
                acc[r][3] = fmaf(ar[r], wv.w, acc[r][3]);
            }
        }

        if (LAYER == 1) {
            #pragma unroll
            for (int r = 0; r < 8; ++r) {
                int row = row0 + rg * 8 + r;
                if (row < n) {
                    float4 v;
                    v.x = fmaxf(acc[r][0] + s_bias[col + 0], 0.f);
                    v.y = fmaxf(acc[r][1] + s_bias[col + 1], 0.f);
                    v.z = fmaxf(acc[r][2] + s_bias[col + 2], 0.f);
                    v.w = fmaxf(acc[r][3] + s_bias[col + 3], 0.f);
                    *reinterpret_cast<float4*>(g_scratch + (size_t)row * D + col) = v;
                }
            }
        } else {
            #pragma unroll
            for (int r = 0; r < 8; ++r) {
                int row = row0 + rg * 8 + r;
                if (row < n) {
                    float v0 = acc[r][0] + s_bias[col + 0];
                    float v1 = acc[r][1] + s_bias[col + 1];
                    float v2 = acc[r][2] + s_bias[col + 2];
                    float v3 = acc[r][3] + s_bias[col + 3];
                    float s = v0 + v1 + v2 + v3;
                    float q = v0*v0 + v1*v1 + v2*v2 + v3*v3;
                    #pragma unroll
                    for (int m = 16; m >= 1; m >>= 1) {
                        s += __shfl_xor_sync(0xffffffffu, s, m);
                        q += __shfl_xor_sync(0xffffffffu, q, m);
                    }
                    float mean = s * (1.f / 128.f);
                    float var  = q * (1.f / 128.f) - mean * mean;
                    float rs   = rsqrtf(var + EPS);
                    v0 = (v0 - mean) * rs * s_g[col + 0] + s_b[col + 0];
                    v1 = (v1 - mean) * rs * s_g[col + 1] + s_b[col + 1];
                    v2 = (v2 - mean) * rs * s_g[col + 2] + s_b[col + 2];
                    v3 = (v3 - mean) * rs * s_g[col + 3] + s_b[col + 3];
                    *reinterpret_cast<float4*>(g_scratch + (size_t)row * D + col) =
                        make_float4(v0, v1, v2, v3);
                }
            }
        }
    }
}

// ---------------------------------------------------------------------------
__global__ __launch_bounds__(256) void chan_stats_kernel(int n) {
    __shared__ float ss[D], sq[D];
    int tid = threadIdx.x;
    if (tid < D) { ss[tid] = 0.f; sq[tid] = 0.f; }
    __syncthreads();

    int c4 = tid & 31;
    int gwarp  = (blockIdx.x * blockDim.x + tid) >> 5;
    int nwarps = (gridDim.x * blockDim.x) >> 5;
    float4 s = make_float4(0.f, 0.f, 0.f, 0.f);
    float4 q = make_float4(0.f, 0.f, 0.f, 0.f);
    for (int r = gwarp; r < n; r += nwarps) {
        float4 v = reinterpret_cast<const float4*>(g_scratch)[(size_t)r * 32 + c4];
        s.x += v.x; s.y += v.y; s.z += v.z; s.w += v.w;
        q.x += v.x * v.x; q.y += v.y * v.y; q.z += v.z * v.z; q.w += v.w * v.w;
    }
    atomicAdd(&ss[c4 * 4 + 0], s.x); atomicAdd(&sq[c4 * 4 + 0], q.x);
    atomicAdd(&ss[c4 * 4 + 1], s.y); atomicAdd(&sq[c4 * 4 + 1], q.y);
    atomicAdd(&ss[c4 * 4 + 2], s.z); atomicAdd(&sq[c4 * 4 + 2], q.z);
    atomicAdd(&ss[c4 * 4 + 3], s.w); atomicAdd(&sq[c4 * 4 + 3], q.w);
    __syncthreads();
    if (tid < D) {
        atomicAdd(&g_chsum[tid], ss[tid]);
        atomicAdd(&g_chsumsq[tid], sq[tid]);
    }
}

// ---------------------------------------------------------------------------
__global__ void gn_stats_kernel(
    const float* __restrict__ gn_w,
    const float* __restrict__ gn_b,
    const float* __restrict__ gn_ms,
    int n
) {
    int j = threadIdx.x;
    float inv_n = 1.f / (float)n;
    float mu  = g_chsum[j] * inv_n;
    float eh2 = g_chsumsq[j] * inv_n;
    float a   = gn_ms[j];
    float var = eh2 - (2.f * a - a * a) * mu * mu;
    float inv = rsqrtf(var + EPS);
    float s   = inv * gn_w[j];
    g_sc[j] = s;
    g_sh[j] = gn_b[j] - a * mu * s;
}

// ---------------------------------------------------------------------------
__global__ void final_kernel(const float* __restrict__ node, float* __restrict__ out, int total4) {
    __shared__ float s_sc[D], s_sh[D];
    if (threadIdx.x < D) {
        s_sc[threadIdx.x] = g_sc[threadIdx.x];
        s_sh[threadIdx.x] = g_sh[threadIdx.x];
    }
    __syncthreads();
    int stride = gridDim.x * blockDim.x;
    for (int i = blockIdx.x * blockDim.x + threadIdx.x; i < total4; i += stride) {
        float4 hv = reinterpret_cast<const float4*>(g_scratch)[i];
        float4 nv = reinterpret_cast<const float4*>(node)[i];
        int j = (i & 31) * 4;
        float4 o;
        o.x = fmaxf(hv.x * s_sc[j + 0] + s_sh[j + 0], 0.f) + nv.x;
        o.y = fmaxf(hv.y * s_sc[j + 1] + s_sh[j + 1], 0.f) + nv.y;
        o.z = fmaxf(hv.z * s_sc[j + 2] + s_sh[j + 2], 0.f) + nv.z;
        o.w = fmaxf(hv.w * s_sc[j + 3] + s_sh[j + 3], 0.f) + nv.w;
        reinterpret_cast<float4*>(out)[i] = o;
    }
}

// ---------------------------------------------------------------------------
extern "C" void kernel_launch(void* const* d_in, const int* in_sizes, int n_in,
                              void* d_out, int out_size) {
    const float* node  = (const float*)d_in[0];
    const float* edgeh = (const float*)d_in[1];
    const float* w1    = (const float*)d_in[2];
    const float* b1    = (const float*)d_in[3];
    const float* w2    = (const float*)d_in[4];
    const float* b2    = (const float*)d_in[5];
    const float* lng   = (const float*)d_in[6];
    const float* lnb   = (const float*)d_in[7];
    const float* gnw   = (const float*)d_in[8];
    const float* gnb   = (const float*)d_in[9];
    const float* gnms  = (const float*)d_in[10];
    const void*  idx   = d_in[11];

    int n = in_sizes[0] / D;   // 50000
    int e = in_sizes[1] / D;   // 600000

    cudaFuncSetAttribute(gemm_tc<1>, cudaFuncAttributeMaxDynamicSharedMemorySize, GEMM_DYN_BYTES);
    cudaFuncSetAttribute(gemm_tc<2>, cudaFuncAttributeMaxDynamicSharedMemorySize, GEMM_DYN_BYTES);
    cudaFuncSetAttribute(gemm_simt<1>, cudaFuncAttributeMaxDynamicSharedMemorySize, SIMT_SMEM_BYTES);
    cudaFuncSetAttribute(gemm_simt<2>, cudaFuncAttributeMaxDynamicSharedMemorySize, SIMT_SMEM_BYTES);

    detect_idx_kernel<<<1, 1>>>((const long long*)idx, n);
    zero_kernel<<<2048, 256>>>(n * (D / 4));
    scatter_kernel<<<(e + 7) / 8, 256>>>(node, edgeh, idx, e);
    gemm_tc<1><<<148, 256, GEMM_DYN_BYTES>>>(w1, b1, lng, lnb, n);
    gemm_simt<1><<<304, 256, SIMT_SMEM_BYTES>>>(w1, b1, lng, lnb, n);
    gemm_tc<2><<<148, 256, GEMM_DYN_BYTES>>>(w2, b2, lng, lnb, n);
    gemm_simt<2><<<304, 256, SIMT_SMEM_BYTES>>>(w2, b2, lng, lnb, n);
    chan_stats_kernel<<<148, 256>>>(n);
    gn_stats_kernel<<<1, D>>>(gnw, gnb, gnms, n);
    final_kernel<<<2048, 256>>>(node, (float*)d_out, n * (D / 4));
}

// round 8
// speedup vs baseline: 1.3174x; 1.2014x over previous
#include <cuda_runtime.h>
#include <cstdint>
#include <cstddef>

#define D 128
#define EPS 1e-5f
#define MAX_NODES 51200

#if defined(__CUDA_ARCH__) && defined(__CUDA_ARCH_FEAT_SM103_ALL)
#define HAS_TCGEN05 1
#else
#define HAS_TCGEN05 0
#endif

// Scratch reused in-place: agg -> h
__device__ float g_scratch[(size_t)MAX_NODES * D];
__device__ float g_chsum[D];
__device__ float g_chsumsq[D];
__device__ float g_sc[D];
__device__ float g_sh[D];
__device__ int   g_idx64;
__device__ int   g_use_tc;

// ---------------------------------------------------------------------------
__device__ __forceinline__ uint32_t smem_u32(const void* p) {
    uint32_t a;
    asm("{ .reg .u64 t; cvta.to.shared.u64 t, %1; cvt.u32.u64 %0, t; }" : "=r"(a) : "l"(p));
    return a;
}
__device__ __forceinline__ uint32_t sw128(uint32_t off) { return off ^ ((off >> 3) & 0x70u); }

#if HAS_TCGEN05
#define TC_ALLOC(smem_addr, ncols) \
    asm volatile("tcgen05.alloc.cta_group::1.sync.aligned.shared::cta.b32 [%0], %1;" \
        :: "r"(smem_addr), "r"((uint32_t)(ncols)) : "memory")
#define TC_DEALLOC(tmem, ncols) \
    asm volatile("tcgen05.dealloc.cta_group::1.sync.aligned.b32 %0, %1;" \
        :: "r"(tmem), "r"((uint32_t)(ncols)))
#define TC_COMMIT(mbar) \
    asm volatile("tcgen05.commit.cta_group::1.mbarrier::arrive::one.shared::cluster.b64 [%0];" \
        :: "r"(mbar) : "memory")
#define TC_FENCE_AFTER()  asm volatile("tcgen05.fence::after_thread_sync;" ::: "memory")
#define TC_FENCE_BEFORE() asm volatile("tcgen05.fence::before_thread_sync;" ::: "memory")
#define TC_WAIT_LD()      asm volatile("tcgen05.wait::ld.sync.aligned;" ::: "memory")

__device__ __forceinline__ void mma_tf32_ss(uint32_t d, uint64_t a, uint64_t b,
                                            uint32_t idesc, bool acc) {
    uint32_t en = acc ? 1u : 0u;
    asm volatile(
        "{\n\t.reg .pred p;\n\t"
        "setp.ne.u32 p, %4, 0;\n\t"
        "tcgen05.mma.cta_group::1.kind::tf32 [%0], %1, %2, %3, {%5, %5, %5, %5}, p;\n\t}"
        :: "r"(d), "l"(a), "l"(b), "r"(idesc), "r"(en), "r"(0u) : "memory");
}

#define LDTM_X32(r, addr) \
    asm volatile( \
        "tcgen05.ld.sync.aligned.32x32b.x32.b32 " \
        "{%0, %1, %2, %3, %4, %5, %6, %7, " \
        " %8, %9, %10, %11, %12, %13, %14, %15, " \
        " %16, %17, %18, %19, %20, %21, %22, %23, " \
        " %24, %25, %26, %27, %28, %29, %30, %31}, [%32];" \
        : "=r"((r)[0]),  "=r"((r)[1]),  "=r"((r)[2]),  "=r"((r)[3]), \
          "=r"((r)[4]),  "=r"((r)[5]),  "=r"((r)[6]),  "=r"((r)[7]), \
          "=r"((r)[8]),  "=r"((r)[9]),  "=r"((r)[10]), "=r"((r)[11]), \
          "=r"((r)[12]), "=r"((r)[13]), "=r"((r)[14]), "=r"((r)[15]), \
          "=r"((r)[16]), "=r"((r)[17]), "=r"((r)[18]), "=r"((r)[19]), \
          "=r"((r)[20]), "=r"((r)[21]), "=r"((r)[22]), "=r"((r)[23]), \
          "=r"((r)[24]), "=r"((r)[25]), "=r"((r)[26]), "=r"((r)[27]), \
          "=r"((r)[28]), "=r"((r)[29]), "=r"((r)[30]), "=r"((r)[31]) \
        : "r"(addr))
#endif  // HAS_TCGEN05

#define MBAR_INIT(mbar, cnt) \
    asm volatile("mbarrier.init.shared.b64 [%0], %1;" :: "r"(mbar), "r"((uint32_t)(cnt)) : "memory")

__device__ __forceinline__ void mbar_wait(uint32_t mbar, uint32_t parity) {
    asm volatile(
        "{\n\t.reg .pred P;\n\t"
        "WL_%=:\n\t"
        "mbarrier.try_wait.parity.acquire.cta.shared::cta.b64 P, [%0], %1, 0x989680;\n\t"
        "@P bra.uni WD_%=;\n\t"
        "bra.uni WL_%=;\n\t"
        "WD_%=:\n\t}"
        :: "r"(mbar), "r"(parity) : "memory");
}

// SMEM descriptor: SW128, version=1, SBO=64, LBO=1 (K-major)
static __device__ __forceinline__ uint64_t make_desc(uint32_t addr) {
    return (uint64_t(2) << 61) | (uint64_t(1) << 46) | (uint64_t(64) << 32)
         | (uint64_t(1) << 16) | ((uint64_t)(addr >> 4) & 0x3FFF);
}

// idesc: c=F32(1<<4), a=TF32(2<<7), b=TF32(2<<10), N=128 (16<<17), M=128 (8<<24)
#define IDESC_TF32 0x8200910u

// ---------------------------------------------------------------------------
__global__ void detect_idx_kernel(const long long* idx, int n_nodes) {
    int ok = 1;
    for (int i = 0; i < 64; ++i) {
        long long v = idx[i];
        if (v < 0 || v >= n_nodes) { ok = 0; break; }
    }
    g_idx64 = ok;
    g_use_tc = HAS_TCGEN05;
}

// ---------------------------------------------------------------------------
__global__ void zero_kernel(int total4) {
    float4* p = reinterpret_cast<float4*>(g_scratch);
    int stride = gridDim.x * blockDim.x;
    for (int i = blockIdx.x * blockDim.x + threadIdx.x; i < total4; i += stride)
        p[i] = make_float4(0.f, 0.f, 0.f, 0.f);
    if (blockIdx.x == 0 && threadIdx.x < D) {
        g_chsum[threadIdx.x] = 0.f;
        g_chsumsq[threadIdx.x] = 0.f;
    }
}

// ---------------------------------------------------------------------------
// One warp per edge: 32 lanes x float4 = 128 floats.
__global__ __launch_bounds__(256) void scatter_kernel(
    const float* __restrict__ node,
    const float* __restrict__ edge_h,
    const void* __restrict__ idx,
    int n_edges
) {
    int e    = (blockIdx.x * blockDim.x + threadIdx.x) >> 5;
    int lane = threadIdx.x & 31;
    if (e >= n_edges) return;

    long long src, dst;
    if (g_idx64) {
        const long long* p = reinterpret_cast<const long long*>(idx);
        src = p[e];
        dst = p[n_edges + e];
    } else {
        const int* p = reinterpret_cast<const int*>(idx);
        src = p[e];
        dst = p[n_edges + e];
    }

    float4 a = reinterpret_cast<const float4*>(node + (size_t)src * D)[lane];
    float4 b = reinterpret_cast<const float4*>(edge_h + (size_t)e * D)[lane];
    float4 m = make_float4(a.x + b.x, a.y + b.y, a.z + b.z, a.w + b.w);
    atomicAdd(reinterpret_cast<float4*>(g_scratch + (size_t)dst * D) + lane, m);
}

// ---------------------------------------------------------------------------
// FUSED MLP: both GEMM layers + bias/ReLU + LayerNorm in one kernel.
// SMEM: W1^T (64KB) + W2^T (64KB) + shared A/h1 buffer (64KB).
// TMEM: D1 = cols 0-127, D2 = cols 128-255.
// Per tile: load agg -> MMA1 -> D1; epi1 (bias+relu) -> h1 back into same smem
// buffer; MMA2 -> D2; epi2 (bias+LayerNorm) -> g_scratch.
#define FUSED_DYN_BYTES (3 * 128 * 128 * 4 + 1024)

__global__ __launch_bounds__(256, 1) void fused_mlp_tc(
    const float* __restrict__ w1,
    const float* __restrict__ b1,
    const float* __restrict__ w2,
    const float* __restrict__ b2,
    const float* __restrict__ lng,
    const float* __restrict__ lnb,
    int n
) {
#if HAS_TCGEN05
    extern __shared__ float dyn[];
    uintptr_t abase = ((uintptr_t)dyn + 1023) & ~(uintptr_t)1023;
    float* w1_s = (float*)abase;        // W1^T swizzled
    float* w2_s = w1_s + 128 * 128;     // W2^T swizzled
    float* ab   = w2_s + 128 * 128;     // A tile / h1 tile (shared)
    __shared__ float s_b1[D], s_b2[D], s_g[D], s_b[D];
    __shared__ float s_sum[256], s_sq[256];
    __shared__ uint32_t s_tmem;
    __shared__ __align__(8) unsigned long long s_mbar[2];

    int tid  = threadIdx.x;
    int wid  = tid >> 5;
    int lane = tid & 31;
    uint32_t mb1 = smem_u32(&s_mbar[0]);
    uint32_t mb2 = smem_u32(&s_mbar[1]);

    if (wid == 0) TC_ALLOC(smem_u32(&s_tmem), 256);
    if (tid == 0) { MBAR_INIT(mb1, 1); MBAR_INIT(mb2, 1); }
    if (tid < D) {
        s_b1[tid] = b1[tid];
        s_b2[tid] = b2[tid];
        s_g[tid]  = lng[tid];
        s_b[tid]  = lnb[tid];
    }

    // ---- prologue: stage + transpose-swizzle both weight matrices
    const float* wsrc[2] = { w1, w2 };
    float* wdst[2] = { w1_s, w2_s };
    for (int m = 0; m < 2; ++m) {
        for (int i = tid; i < 4096; i += 256)
            reinterpret_cast<float4*>(ab)[i] = reinterpret_cast<const float4*>(wsrc[m])[i];
        __syncthreads();
        float* wd = wdst[m];
        for (int i = tid; i < 4096; i += 256) {
            int kc = i >> 7, nn = i & 127;
            int k0 = kc * 4;
            float4 v;
            v.x = ab[(k0 + 0) * 128 + nn];
            v.y = ab[(k0 + 1) * 128 + nn];
            v.z = ab[(k0 + 2) * 128 + nn];
            v.w = ab[(k0 + 3) * 128 + nn];
            uint32_t off = ((uint32_t)(nn >> 3) + (uint32_t)(k0 >> 5) * 16u) * 1024u
                         + (uint32_t)(nn & 7) * 128u + (uint32_t)(k0 & 31) * 4u;
            *reinterpret_cast<float4*>(reinterpret_cast<char*>(wd) + sw128(off)) = v;
        }
        __syncthreads();
    }

    uint32_t tmem = s_tmem;
    uint64_t ab_desc = make_desc(smem_u32(ab));
    uint64_t w1_desc = make_desc(smem_u32(w1_s));
    uint64_t w2_desc = make_desc(smem_u32(w2_s));
    int ntiles = (n + 127) >> 7;

    int w4  = wid & 3;           // epilogue: row = w4*32+lane
    int cb0 = (wid >> 2) * 64;   // warps 0-3 cols 0-63, warps 4-7 cols 64-127
    uint32_t ph1 = 0, ph2 = 0;

    for (int tile = blockIdx.x; tile < ntiles; tile += gridDim.x) {
        int row0 = tile << 7;

        // ---- load agg tile into ab (swizzled)
        for (int i = tid; i < 4096; i += 256) {
            int r = i >> 5, c4 = i & 31;
            int k0 = c4 * 4;
            int row = row0 + r;
            float4 v = make_float4(0.f, 0.f, 0.f, 0.f);
            if (row < n) v = *reinterpret_cast<const float4*>(g_scratch + (size_t)row * D + k0);
            uint32_t off = ((uint32_t)(r >> 3) + (uint32_t)(k0 >> 5) * 16u) * 1024u
                         + (uint32_t)(r & 7) * 128u + (uint32_t)(k0 & 31) * 4u;
            *reinterpret_cast<float4*>(reinterpret_cast<char*>(ab) + sw128(off)) = v;
        }
        asm volatile("fence.proxy.async.shared::cta;" ::: "memory");
        __syncthreads();

        // ---- MMA layer 1 -> D1 (tmem + 0)
        if (tid == 0) {
            #pragma unroll
            for (int t = 0; t < 16; ++t) {
                uint64_t off = (uint64_t)((t >> 2) * 1024 + (t & 3) * 2);
                mma_tf32_ss(tmem, ab_desc + off, w1_desc + off, IDESC_TF32, t > 0);
            }
            TC_COMMIT(mb1);
        }
        mbar_wait(mb1, ph1);
        ph1 ^= 1;
        TC_FENCE_AFTER();

        // ---- epilogue 1: bias + relu, h1 back into ab (swizzled)
        {
            int r = w4 * 32 + lane;
            uint32_t r32[64];
            LDTM_X32(r32,      tmem + cb0);
            LDTM_X32(r32 + 32, tmem + cb0 + 32);
            TC_WAIT_LD();
            #pragma unroll
            for (int j = 0; j < 16; ++j) {
                int k0 = cb0 + 4 * j;
                float4 v;
                v.x = fmaxf(__uint_as_float(r32[4*j+0]) + s_b1[k0 + 0], 0.f);
                v.y = fmaxf(__uint_as_float(r32[4*j+1]) + s_b1[k0 + 1], 0.f);
                v.z = fmaxf(__uint_as_float(r32[4*j+2]) + s_b1[k0 + 2], 0.f);
                v.w = fmaxf(__uint_as_float(r32[4*j+3]) + s_b1[k0 + 3], 0.f);
                uint32_t off = ((uint32_t)(r >> 3) + (uint32_t)(k0 >> 5) * 16u) * 1024u
                             + (uint32_t)(r & 7) * 128u + (uint32_t)(k0 & 31) * 4u;
                *reinterpret_cast<float4*>(reinterpret_cast<char*>(ab) + sw128(off)) = v;
            }
        }
        TC_FENCE_BEFORE();
        asm volatile("fence.proxy.async.shared::cta;" ::: "memory");
        __syncthreads();

        // ---- MMA layer 2 -> D2 (tmem + 128)
        if (tid == 0) {
            #pragma unroll
            for (int t = 0; t < 16; ++t) {
                uint64_t off = (uint64_t)((t >> 2) * 1024 + (t & 3) * 2);
                mma_tf32_ss(tmem + 128u, ab_desc + off, w2_desc + off, IDESC_TF32, t > 0);
            }
            TC_COMMIT(mb2);
        }
        mbar_wait(mb2, ph2);
        ph2 ^= 1;
        TC_FENCE_AFTER();

        // ---- epilogue 2: bias + LayerNorm -> g_scratch
        {
            int row = row0 + w4 * 32 + lane;
            uint32_t r32[64];
            LDTM_X32(r32,      tmem + 128u + cb0);
            LDTM_X32(r32 + 32, tmem + 128u + cb0 + 32);
            TC_WAIT_LD();

            float sum = 0.f, sq = 0.f;
            #pragma unroll
            for (int c = 0; c < 64; ++c) {
                float v = __uint_as_float(r32[c]) + s_b2[cb0 + c];
                r32[c] = __float_as_uint(v);
                sum += v;
                sq  += v * v;
            }
            s_sum[tid] = sum;
            s_sq[tid]  = sq;
            __syncthreads();
            float S = s_sum[tid] + s_sum[tid ^ 128];
            float Q = s_sq[tid]  + s_sq[tid ^ 128];
            float mean = S * (1.f / 128.f);
            float var  = Q * (1.f / 128.f) - mean * mean;
            float rs   = rsqrtf(var + EPS);
            if (row < n) {
                float* dst = g_scratch + (size_t)row * D + cb0;
                #pragma unroll
                for (int j = 0; j < 16; ++j) {
                    float4 v;
                    v.x = (__uint_as_float(r32[4*j+0]) - mean) * rs * s_g[cb0+4*j+0] + s_b[cb0+4*j+0];
                    v.y = (__uint_as_float(r32[4*j+1]) - mean) * rs * s_g[cb0+4*j+1] + s_b[cb0+4*j+1];
                    v.z = (__uint_as_float(r32[4*j+2]) - mean) * rs * s_g[cb0+4*j+2] + s_b[cb0+4*j+2];
                    v.w = (__uint_as_float(r32[4*j+3]) - mean) * rs * s_g[cb0+4*j+3] + s_b[cb0+4*j+3];
                    reinterpret_cast<float4*>(dst)[j] = v;
                }
            }
        }
        TC_FENCE_BEFORE();
        __syncthreads();   // s_sum reuse + ab overwrite safety for next tile
    }

    __syncthreads();
    if (wid == 0) TC_DEALLOC(tmem, 256);
#endif  // HAS_TCGEN05
}

// ---------------------------------------------------------------------------
// SIMT fallback GEMM (runs only when g_use_tc == 0).
#define TILE_ROWS 64
#define A_LD 68
#define SIMT_SMEM_FLOATS (128*128 + 128*A_LD)
#define SIMT_SMEM_BYTES  (SIMT_SMEM_FLOATS * sizeof(float))

template<int LAYER>
__global__ __launch_bounds__(256, 2) void gemm_simt(
    const float* __restrict__ w,
    const float* __restrict__ bias,
    const float* __restrict__ lng,
    const float* __restrict__ lnb,
    int n
) {
    if (g_use_tc) return;
    extern __shared__ float sm[];
    float* w_s  = sm;
    float* a_s  = sm + 128 * 128;
    __shared__ float s_bias[D], s_g[D], s_b[D];

    int tid = threadIdx.x;
    for (int i = tid; i < 128 * 128; i += 256) w_s[i] = w[i];
    if (tid < D) {
        s_bias[tid] = bias[tid];
        if (LAYER == 2) { s_g[tid] = lng[tid]; s_b[tid] = lnb[tid]; }
    }

    int col = (tid & 31) * 4;
    int rg  = tid >> 5;
    int num_tiles = (n + TILE_ROWS - 1) / TILE_ROWS;

    for (int tile = blockIdx.x; tile < num_tiles; tile += gridDim.x) {
        int row0 = tile * TILE_ROWS;
        __syncthreads();
        for (int i = tid; i < TILE_ROWS * 128; i += 256) {
            int r = i >> 7, k = i & 127;
            int row = row0 + r;
            a_s[k * A_LD + r] = (row < n) ? g_scratch[(size_t)row * D + k] : 0.f;
        }
        __syncthreads();

        float acc[8][4];
        #pragma unroll
        for (int r = 0; r < 8; ++r)
            #pragma unroll
            for (int c = 0; c < 4; ++c) acc[r][c] = 0.f;

        #pragma unroll 8
        for (int k = 0; k < 128; ++k) {
            float4 wv = *reinterpret_cast<const float4*>(w_s + k * 128 + col);
            float4 aa = *reinterpret_cast<const float4*>(a_s + k * A_LD + rg * 8);
            float4 ab2 = *reinterpret_cast<const float4*>(a_s + k * A_LD + rg * 8 + 4);
            float ar[8] = {aa.x, aa.y, aa.z, aa.w, ab2.x, ab2.y, ab2.z, ab2.w};
            #pragma unroll
            for (int r = 0; r < 8; ++r) {
                acc[r][0] = fmaf(ar[r], wv.x, acc[r][0]);
                acc[r][1] = fmaf(ar[r], wv.y, acc[r][1]);
                acc[r][2] = fmaf(ar[r], wv.z, acc[r][2]);
                acc[r][3] = fmaf(ar[r], wv.w, acc[r][3]);
            }
        }

        if (LAYER == 1) {
            #pragma unroll
            for (int r = 0; r < 8; ++r) {
                int row = row0 + rg * 8 + r;
                if (row < n) {
                    float4 v;
                    v.x = fmaxf(acc[r][0] + s_bias[col + 0], 0.f);
                    v.y = fmaxf(acc[r][1] + s_bias[col + 1], 0.f);
                    v.z = fmaxf(acc[r][2] + s_bias[col + 2], 0.f);
                    v.w = fmaxf(acc[r][3] + s_bias[col + 3], 0.f);
                    *reinterpret_cast<float4*>(g_scratch + (size_t)row * D + col) = v;
                }
            }
        } else {
            #pragma unroll
            for (int r = 0; r < 8; ++r) {
                int row = row0 + rg * 8 + r;
                if (row < n) {
                    float v0 = acc[r][0] + s_bias[col + 0];
                    float v1 = acc[r][1] + s_bias[col + 1];
                    float v2 = acc[r][2] + s_bias[col + 2];
                    float v3 = acc[r][3] + s_bias[col + 3];
                    float s = v0 + v1 + v2 + v3;
                    float q = v0*v0 + v1*v1 + v2*v2 + v3*v3;
                    #pragma unroll
                    for (int m = 16; m >= 1; m >>= 1) {
                        s += __shfl_xor_sync(0xffffffffu, s, m);
                        q += __shfl_xor_sync(0xffffffffu, q, m);
                    }
                    float mean = s * (1.f / 128.f);
                    float var  = q * (1.f / 128.f) - mean * mean;
                    float rs   = rsqrtf(var + EPS);
                    v0 = (v0 - mean) * rs * s_g[col + 0] + s_b[col + 0];
                    v1 = (v1 - mean) * rs * s_g[col + 1] + s_b[col + 1];
                    v2 = (v2 - mean) * rs * s_g[col + 2] + s_b[col + 2];
                    v3 = (v3 - mean) * rs * s_g[col + 3] + s_b[col + 3];
                    *reinterpret_cast<float4*>(g_scratch + (size_t)row * D + col) =
                        make_float4(v0, v1, v2, v3);
                }
            }
        }
    }
}

// ---------------------------------------------------------------------------
__global__ __launch_bounds__(256) void chan_stats_kernel(int n) {
    __shared__ float ss[D], sq[D];
    int tid = threadIdx.x;
    if (tid < D) { ss[tid] = 0.f; sq[tid] = 0.f; }
    __syncthreads();

    int c4 = tid & 31;
    int gwarp  = (blockIdx.x * blockDim.x + tid) >> 5;
    int nwarps = (gridDim.x * blockDim.x) >> 5;
    float4 s = make_float4(0.f, 0.f, 0.f, 0.f);
    float4 q = make_float4(0.f, 0.f, 0.f, 0.f);
    for (int r = gwarp; r < n; r += nwarps) {
        float4 v = reinterpret_cast<const float4*>(g_scratch)[(size_t)r * 32 + c4];
        s.x += v.x; s.y += v.y; s.z += v.z; s.w += v.w;
        q.x += v.x * v.x; q.y += v.y * v.y; q.z += v.z * v.z; q.w += v.w * v.w;
    }
    atomicAdd(&ss[c4 * 4 + 0], s.x); atomicAdd(&sq[c4 * 4 + 0], q.x);
    atomicAdd(&ss[c4 * 4 + 1], s.y); atomicAdd(&sq[c4 * 4 + 1], q.y);
    atomicAdd(&ss[c4 * 4 + 2], s.z); atomicAdd(&sq[c4 * 4 + 2], q.z);
    atomicAdd(&ss[c4 * 4 + 3], s.w); atomicAdd(&sq[c4 * 4 + 3], q.w);
    __syncthreads();
    if (tid < D) {
        atomicAdd(&g_chsum[tid], ss[tid]);
        atomicAdd(&g_chsumsq[tid], sq[tid]);
    }
}

// ---------------------------------------------------------------------------
__global__ void gn_stats_kernel(
    const float* __restrict__ gn_w,
    const float* __restrict__ gn_b,
    const float* __restrict__ gn_ms,
    int n
) {
    int j = threadIdx.x;
    float inv_n = 1.f / (float)n;
    float mu  = g_chsum[j] * inv_n;
    float eh2 = g_chsumsq[j] * inv_n;
    float a   = gn_ms[j];
    float var = eh2 - (2.f * a - a * a) * mu * mu;
    float inv = rsqrtf(var + EPS);
    float s   = inv * gn_w[j];
    g_sc[j] = s;
    g_sh[j] = gn_b[j] - a * mu * s;
}

// ---------------------------------------------------------------------------
__global__ void final_kernel(const float* __restrict__ node, float* __restrict__ out, int total4) {
    __shared__ float s_sc[D], s_sh[D];
    if (threadIdx.x < D) {
        s_sc[threadIdx.x] = g_sc[threadIdx.x];
        s_sh[threadIdx.x] = g_sh[threadIdx.x];
    }
    __syncthreads();
    int stride = gridDim.x * blockDim.x;
    for (int i = blockIdx.x * blockDim.x + threadIdx.x; i < total4; i += stride) {
        float4 hv = reinterpret_cast<const float4*>(g_scratch)[i];
        float4 nv = reinterpret_cast<const float4*>(node)[i];
        int j = (i & 31) * 4;
        float4 o;
        o.x = fmaxf(hv.x * s_sc[j + 0] + s_sh[j + 0], 0.f) + nv.x;
        o.y = fmaxf(hv.y * s_sc[j + 1] + s_sh[j + 1], 0.f) + nv.y;
        o.z = fmaxf(hv.z * s_sc[j + 2] + s_sh[j + 2], 0.f) + nv.z;
        o.w = fmaxf(hv.w * s_sc[j + 3] + s_sh[j + 3], 0.f) + nv.w;
        reinterpret_cast<float4*>(out)[i] = o;
    }
}

// ---------------------------------------------------------------------------
extern "C" void kernel_launch(void* const* d_in, const int* in_sizes, int n_in,
                              void* d_out, int out_size) {
    const float* node  = (const float*)d_in[0];
    const float* edgeh = (const float*)d_in[1];
    const float* w1    = (const float*)d_in[2];
    const float* b1    = (const float*)d_in[3];
    const float* w2    = (const float*)d_in[4];
    const float* b2    = (const float*)d_in[5];
    const float* lng   = (const float*)d_in[6];
    const float* lnb   = (const float*)d_in[7];
    const float* gnw   = (const float*)d_in[8];
    const float* gnb   = (const float*)d_in[9];
    const float* gnms  = (const float*)d_in[10];
    const void*  idx   = d_in[11];

    int n = in_sizes[0] / D;   // 50000
    int e = in_sizes[1] / D;   // 600000

    cudaFuncSetAttribute(fused_mlp_tc, cudaFuncAttributeMaxDynamicSharedMemorySize, FUSED_DYN_BYTES);
    cudaFuncSetAttribute(gemm_simt<1>, cudaFuncAttributeMaxDynamicSharedMemorySize, SIMT_SMEM_BYTES);
    cudaFuncSetAttribute(gemm_simt<2>, cudaFuncAttributeMaxDynamicSharedMemorySize, SIMT_SMEM_BYTES);

    detect_idx_kernel<<<1, 1>>>((const long long*)idx, n);
    zero_kernel<<<2048, 256>>>(n * (D / 4));
    scatter_kernel<<<(e + 7) / 8, 256>>>(node, edgeh, idx, e);
    fused_mlp_tc<<<148, 256, FUSED_DYN_BYTES>>>(w1, b1, w2, b2, lng, lnb, n);
    gemm_simt<1><<<304, 256, SIMT_SMEM_BYTES>>>(w1, b1, lng, lnb, n);
    gemm_simt<2><<<304, 256, SIMT_SMEM_BYTES>>>(w2, b2, lng, lnb, n);
    chan_stats_kernel<<<148, 256>>>(n);
    gn_stats_kernel<<<1, D>>>(gnw, gnb, gnms, n);
    final_kernel<<<2048, 256>>>(node, (float*)d_out, n * (D / 4));
}